// round 10
// baseline (speedup 1.0000x reference)
#include <cuda_runtime.h>
#include <cuda_bf16.h>

// ---------------------------------------------------------------------------
// HardTripletMiningLoss  (n=3B=480, D=128)
//   gram = E E^T ;  pd[i,j] = max(sq_i + sq_j - 2 gram_ij, 0)
//   loss = mean over {i!=0, lab[i]==lab[j], lab[k]!=lab[j], td>0} of
//          td = pd[i,j] - pd[j,k] + A
// R10: ONE persistent kernel (592 blocks x 384 thr = 4/SM guaranteed
//      co-resident), software grid barriers. Phase1 gram (32x48 tiles,
//      KSPLIT=4, 600 tasks), Phase2 triplet (1 j/block), Phase3 final.
//      Removes 2 launch nodes (~4us) and keeps 75% occupancy in gram.
// ---------------------------------------------------------------------------

#define MAX_N    768
#define MAXW     ((MAX_N + 31) / 32)
#define POSCAP   128
#define MARGIN_A 0.2f
#define NBLOCKS  592      // 4 per SM on 148 SMs
#define NTHREADS 384      // 12 warps
#define NWARP    12
#define TR       32
#define TC       48
#define KSPLIT   4
#define KC       32       // D / KSPLIT for D=128
#define ASTR     36       // As stride, mult of 4 (aligned float4 stores)

static __device__ float    g_part[KSPLIT][MAX_N * MAX_N];
static __device__ float    g_sqp [KSPLIT][MAX_N];
static __device__ float    g_ps[MAX_N];
static __device__ int      g_pc[MAX_N];
static __device__ unsigned g_bar1 = 0;
static __device__ unsigned g_bar2 = 0;

__device__ __forceinline__ const float* row_ptr(const float* a, const float* p,
                                                const float* ng, int r, int B, int D) {
    if (r < B)      return a  + (size_t)r * D;
    if (r < 2 * B)  return p  + (size_t)(r - B) * D;
    return ng + (size_t)(r - 2 * B) * D;
}

__global__ void __launch_bounds__(NTHREADS, 4)
fused_kernel(const float* __restrict__ anchor,
             const float* __restrict__ positive,
             const float* __restrict__ negative,
             const int*   __restrict__ ind,
             float* __restrict__ out,
             int n, int B, int D) {
    __shared__ float    As[TR][ASTR];      // row-major over k
    __shared__ float    BsT[KC][TC];       // k-major (transposed)
    __shared__ float    pdrow[MAX_N];
    __shared__ int      labs[MAX_N];
    __shared__ float    avals[POSCAP];
    __shared__ unsigned chunkMask[MAXW];
    __shared__ int      chunkOff[MAXW];
    __shared__ int      nSame;
    __shared__ float    red_s[NWARP];
    __shared__ int      red_c[NWARP];
    __shared__ double   fred_s[NWARP];
    __shared__ double   fred_c[NWARP];

    const int tid  = threadIdx.x;
    const int lane = tid & 31;
    const int wid  = tid >> 5;

    // =========================== Phase 1: gram ==============================
    const int nTR = (n + TR - 1) / TR;
    const int nTC = (n + TC - 1) / TC;
    const int nTasks = nTR * nTC * KSPLIT;
    const int Kc  = D / KSPLIT;
    const int nf4 = Kc >> 2;                 // 8

    for (int task = blockIdx.x; task < nTasks; task += gridDim.x) {
        const int z   = task & (KSPLIT - 1);
        const int tmp = task >> 2;           // KSPLIT == 4
        const int tc  = tmp % nTC;
        const int tr  = tmp / nTC;
        const int bi  = tr * TR;
        const int bj  = tc * TC;
        const int k0  = z * Kc;

        // load As: TR rows x nf4 float4
        for (int idx = tid; idx < TR * nf4; idx += NTHREADS) {
            const int r  = idx >> 3;
            const int c4 = idx & 7;
            const int gr = (bi + r < n) ? bi + r : n - 1;
            const float4 v = *(const float4*)(row_ptr(anchor, positive, negative, gr, B, D) + k0 + c4 * 4);
            *(float4*)&As[r][c4 * 4] = v;
        }
        // load BsT transposed: TC cols x nf4 float4 (one per thread)
        for (int idx = tid; idx < TC * nf4; idx += NTHREADS) {
            const int c  = idx % TC;
            const int c4 = idx / TC;
            const int gc = (bj + c < n) ? bj + c : n - 1;
            const float4 v = *(const float4*)(row_ptr(anchor, positive, negative, gc, B, D) + k0 + c4 * 4);
            const int k = c4 * 4;
            BsT[k + 0][c] = v.x;
            BsT[k + 1][c] = v.y;
            BsT[k + 2][c] = v.z;
            BsT[k + 3][c] = v.w;
        }
        __syncthreads();

        const int t24 = tid % 24;            // 24 col-pairs
        const int ty  = tid / 24;            // 16 row-pairs
        const int r0  = ty * 2;
        const int c0  = t24 * 2;

        float a00 = 0.f, a01 = 0.f, a10 = 0.f, a11 = 0.f;
        #pragma unroll 8
        for (int k = 0; k < Kc; k++) {
            const float x0 = As[r0][k];                       // broadcast
            const float x1 = As[r0 + 1][k];                   // broadcast
            const float2 b = *(const float2*)&BsT[k][c0];     // conflict-free LDS.64
            a00 = fmaf(x0, b.x, a00);
            a01 = fmaf(x0, b.y, a01);
            a10 = fmaf(x1, b.x, a10);
            a11 = fmaf(x1, b.y, a11);
        }

        float* gp = g_part[z];
        const int gi0 = bi + r0, gi1 = gi0 + 1;
        const int gj0 = bj + c0, gj1 = gj0 + 1;
        if (gj1 < n) {                       // n even -> aligned float2 pairs
            if (gi0 < n) {
                *(float2*)&gp[(size_t)gi0 * n + gj0] = make_float2(a00, a01);
                if      (gi0 == gj0) g_sqp[z][gi0] = a00;
                else if (gi0 == gj1) g_sqp[z][gi0] = a01;
            }
            if (gi1 < n) {
                *(float2*)&gp[(size_t)gi1 * n + gj0] = make_float2(a10, a11);
                if      (gi1 == gj0) g_sqp[z][gi1] = a10;
                else if (gi1 == gj1) g_sqp[z][gi1] = a11;
            }
        } else if (gj0 < n) {
            if (gi0 < n) { gp[(size_t)gi0 * n + gj0] = a00; if (gi0 == gj0) g_sqp[z][gi0] = a00; }
            if (gi1 < n) { gp[(size_t)gi1 * n + gj0] = a10; if (gi1 == gj0) g_sqp[z][gi1] = a10; }
        }
        __syncthreads();   // smem reuse across tasks
    }

    // ======================= grid barrier 1 (all wait) ======================
    __syncthreads();
    if (tid == 0) {
        __threadfence();                     // release this block's gram writes
        atomicAdd(&g_bar1, 1u);
        while (*(volatile unsigned*)&g_bar1 < (unsigned)gridDim.x)
            __nanosleep(256);
        __threadfence();                     // acquire
    }
    __syncthreads();

    // =========================== Phase 2: triplet ===========================
    for (int j = blockIdx.x; j < n; j += gridDim.x) {
        float sqj = g_sqp[0][j];
        #pragma unroll
        for (int z = 1; z < KSPLIT; z++) sqj += g_sqp[z][j];

        const size_t roff = (size_t)j * n;
        const int n4 = n >> 2;
        for (int v = tid; v < n4; v += NTHREADS) {
            float4 g = ((const float4*)(g_part[0] + roff))[v];
            float4 q = ((const float4*)g_sqp[0])[v];
            #pragma unroll
            for (int z = 1; z < KSPLIT; z++) {
                const float4 gz = ((const float4*)(g_part[z] + roff))[v];
                const float4 qz = ((const float4*)g_sqp[z])[v];
                g.x += gz.x; g.y += gz.y; g.z += gz.z; g.w += gz.w;
                q.x += qz.x; q.y += qz.y; q.z += qz.z; q.w += qz.w;
            }
            float4 pd;
            pd.x = fmaxf(fmaf(-2.f, g.x, sqj + q.x), 0.f);
            pd.y = fmaxf(fmaf(-2.f, g.y, sqj + q.y), 0.f);
            pd.z = fmaxf(fmaf(-2.f, g.z, sqj + q.z), 0.f);
            pd.w = fmaxf(fmaf(-2.f, g.w, sqj + q.w), 0.f);
            ((float4*)pdrow)[v] = pd;
        }
        for (int v = (n4 << 2) + tid; v < n; v += NTHREADS) {
            float g = 0.f, q = 0.f;
            #pragma unroll
            for (int z = 0; z < KSPLIT; z++) { g += g_part[z][roff + v]; q += g_sqp[z][v]; }
            pdrow[v] = fmaxf(fmaf(-2.f, g, sqj + q), 0.f);
        }
        for (int t = tid; t < n; t += NTHREADS)
            labs[t] = ind[t];
        __syncthreads();

        const int labj = labs[j];
        const int nChunks = (n + 31) >> 5;
        for (int c = wid; c < nChunks; c += NWARP) {
            const int t = (c << 5) + lane;
            const bool pred = (t < n) && (t != 0) && (labs[t] == labj);
            const unsigned m = __ballot_sync(0xffffffffu, pred);
            if (lane == 0) chunkMask[c] = m;
        }
        __syncthreads();
        if (wid == 0) {                       // warp scan (nChunks <= 32)
            const unsigned m = (lane < nChunks) ? chunkMask[lane] : 0u;
            int p = __popc(m);
            #pragma unroll
            for (int o = 1; o < 32; o <<= 1) {
                const int t = __shfl_up_sync(0xffffffffu, p, o);
                if (lane >= o) p += t;
            }
            if (lane < nChunks) chunkOff[lane] = p - __popc(m);
            if (lane == 31) nSame = p;
        }
        __syncthreads();
        for (int c = wid; c < nChunks; c += NWARP) {
            const unsigned m = chunkMask[c];
            const int t = (c << 5) + lane;
            if ((m >> lane) & 1u) {
                const int off = chunkOff[c] + __popc(m & ((1u << lane) - 1u));
                if (off < POSCAP) avals[off] = pdrow[t] + MARGIN_A;
            }
        }
        __syncthreads();

        float pdk0 = 3.4e38f, pdk1 = 3.4e38f;      // sentinels: never counted
        if (tid < n            && labs[tid]            != labj) pdk0 = pdrow[tid];
        if (tid + NTHREADS < n && labs[tid + NTHREADS] != labj) pdk1 = pdrow[tid + NTHREADS];

        const int ns = (nSame < POSCAP) ? nSame : POSCAP;
        float s = 0.f;
        int   c = 0;
        for (int q = 0; q < ns; q++) {
            const float aq = avals[q];
            const float v0 = aq - pdk0;
            const float v1 = aq - pdk1;
            if (v0 > 0.f) { s += v0; c++; }
            if (v1 > 0.f) { s += v1; c++; }
        }

        #pragma unroll
        for (int o = 16; o > 0; o >>= 1) {
            s += __shfl_down_sync(0xffffffffu, s, o);
            c += __shfl_down_sync(0xffffffffu, c, o);
        }
        if (lane == 0) { red_s[wid] = s; red_c[wid] = c; }
        __syncthreads();
        if (tid == 0) {
            float st = 0.f; int ct = 0;
            #pragma unroll
            for (int w = 0; w < NWARP; w++) { st += red_s[w]; ct += red_c[w]; }
            g_ps[j] = st;
            g_pc[j] = ct;
        }
        __syncthreads();   // smem reuse across j's
    }

    // ================= barrier 2 (arrive-only) + final in block 0 ===========
    __syncthreads();
    if (tid == 0) {
        __threadfence();                     // release g_ps / g_pc
        atomicAdd(&g_bar2, 1u);
    }
    if (blockIdx.x != 0) return;            // others exit; no spin -> reset safe

    if (tid == 0) {
        while (*(volatile unsigned*)&g_bar2 < (unsigned)gridDim.x)
            __nanosleep(256);
        __threadfence();                     // acquire
    }
    __syncthreads();

    double s = 0.0, cd = 0.0;
    for (int t = tid; t < n; t += NTHREADS) { s += (double)g_ps[t]; cd += (double)g_pc[t]; }
    #pragma unroll
    for (int o = 16; o > 0; o >>= 1) {
        s  += __shfl_down_sync(0xffffffffu, s, o);
        cd += __shfl_down_sync(0xffffffffu, cd, o);
    }
    if (lane == 0) { fred_s[wid] = s; fred_c[wid] = cd; }
    __syncthreads();
    if (tid == 0) {
        double st = 0.0, ct = 0.0;
        #pragma unroll
        for (int w = 0; w < NWARP; w++) { st += fred_s[w]; ct += fred_c[w]; }
        out[0] = (ct > 0.0) ? (float)(st / (ct < 1.0 ? 1.0 : ct)) : 0.0f;
        g_bar1 = 0;                          // reset for next graph replay
        g_bar2 = 0;
    }
}

extern "C" void kernel_launch(void* const* d_in, const int* in_sizes, int n_in,
                              void* d_out, int out_size) {
    const float* anchor   = (const float*)d_in[0];
    const float* positive = (const float*)d_in[1];
    const float* negative = (const float*)d_in[2];
    const int*   ind      = (const int*)d_in[3];

    const int n = in_sizes[3];          // 3B
    const int B = n / 3;
    const int D = in_sizes[0] / B;      // 128

    fused_kernel<<<NBLOCKS, NTHREADS>>>(anchor, positive, negative, ind,
                                        (float*)d_out, n, B, D);
}

// round 11
// speedup vs baseline: 1.1083x; 1.1083x over previous
#include <cuda_runtime.h>
#include <cuda_bf16.h>

// ---------------------------------------------------------------------------
// HardTripletMiningLoss  (n=3B=480, D=128)
//   gram = E E^T ;  pd[i,j] = max(sq_i + sq_j - 2 gram_ij, 0)
//   loss = mean over {i!=0, lab[i]==lab[j], lab[k]!=lab[j], td>0} of
//          td = pd[i,j] - pd[j,k] + A
// R11: 3 kernels (fusion's grid barrier = same-address atomic storm, ~7us).
//      Gram: 32x64 tile / 2x4 per thread / 256 thr / KSPLIT=8 -> 960 blocks:
//      R8's occupancy AND R9's LDS.128 inner loop (48 LDS/thread vs 128;
//      LDS is the binding pipe per sm_103a LDS->LDS floor).
// ---------------------------------------------------------------------------

#define MAX_N    768
#define MAXW     ((MAX_N + 31) / 32)
#define POSCAP   128
#define MARGIN_A 0.2f
#define TR       32      // tile rows
#define TCN      64      // tile cols
#define KSPLIT   8
#define KC       16      // D / KSPLIT for D=128
#define ASTR     20      // As row stride (mult of 4 -> aligned float4 stores)

static __device__ float g_part[KSPLIT][MAX_N * MAX_N];
static __device__ float g_sqp [KSPLIT][MAX_N];
static __device__ float g_ps[MAX_N];
static __device__ int   g_pc[MAX_N];

__device__ __forceinline__ const float* row_ptr(const float* a, const float* p,
                                                const float* ng, int r, int B, int D) {
    if (r < B)      return a  + (size_t)r * D;
    if (r < 2 * B)  return p  + (size_t)(r - B) * D;
    return ng + (size_t)(r - 2 * B) * D;
}

// ---------------------------------------------------------------------------
// gram: grid (ceil(n/64), ceil(n/32), KSPLIT), 256 thr, 2 rows x 4 cols each.
// Inner loop per k: 2 broadcast LDS + 1 LDS.128 + 8 FMA.
// ---------------------------------------------------------------------------
__global__ void gram_kernel(const float* __restrict__ anchor,
                            const float* __restrict__ positive,
                            const float* __restrict__ negative,
                            int n, int B, int D) {
    __shared__ float As[TR][ASTR];      // row-major over k (2.5 KB)
    __shared__ float BsT[KC][TCN];      // k-major transposed (4 KB)

    const int bi  = blockIdx.y * TR;
    const int bj  = blockIdx.x * TCN;
    const int z   = blockIdx.z;
    const int Kc  = D / KSPLIT;          // 16
    const int k0  = z * Kc;
    const int tid = threadIdx.x;
    const int nf4 = Kc >> 2;             // 4

    // load As: 32 rows x 4 float4 = 128 loads (threads 128-255 idle here)
    if (tid < TR * 4) {
        const int r  = tid >> 2;
        const int c4 = tid & 3;
        const int gr = (bi + r < n) ? bi + r : n - 1;
        const float4 v = *(const float4*)(row_ptr(anchor, positive, negative, gr, B, D) + k0 + c4 * 4);
        *(float4*)&As[r][c4 * 4] = v;
    }
    // load BsT transposed: 64 cols x 4 float4 = 256 loads (one per thread)
    {
        const int col = tid & (TCN - 1);
        const int c4  = tid >> 6;        // 0..3
        const int gc  = (bj + col < n) ? bj + col : n - 1;
        const float4 v = *(const float4*)(row_ptr(anchor, positive, negative, gc, B, D) + k0 + c4 * 4);
        const int k = c4 * 4;
        BsT[k + 0][col] = v.x;
        BsT[k + 1][col] = v.y;
        BsT[k + 2][col] = v.z;
        BsT[k + 3][col] = v.w;
    }
    __syncthreads();

    const int tx = tid & 15;             // 16 col-groups
    const int ty = tid >> 4;             // 16 row-groups
    const int r0 = ty * 2;
    const int c0 = tx * 4;

    float a0x = 0.f, a0y = 0.f, a0z = 0.f, a0w = 0.f;
    float a1x = 0.f, a1y = 0.f, a1z = 0.f, a1w = 0.f;

    #pragma unroll
    for (int k = 0; k < KC; k++) {
        const float x0 = As[r0][k];                      // broadcast LDS
        const float x1 = As[r0 + 1][k];                  // broadcast LDS
        const float4 b = *(const float4*)&BsT[k][c0];    // conflict-free LDS.128
        a0x = fmaf(x0, b.x, a0x);
        a0y = fmaf(x0, b.y, a0y);
        a0z = fmaf(x0, b.z, a0z);
        a0w = fmaf(x0, b.w, a0w);
        a1x = fmaf(x1, b.x, a1x);
        a1y = fmaf(x1, b.y, a1y);
        a1z = fmaf(x1, b.z, a1z);
        a1w = fmaf(x1, b.w, a1w);
    }

    float* gp = g_part[z];
    const int gi0 = bi + r0;
    const int gj0 = bj + c0;
    if (gj0 < n) {                        // n%4==0, gj0%4==0 -> float4 in-bounds
        if (gi0 < n) {
            float4 v; v.x = a0x; v.y = a0y; v.z = a0z; v.w = a0w;
            *(float4*)&gp[(size_t)gi0 * n + gj0] = v;
            const int dq = gi0 - gj0;
            if (dq >= 0 && dq < 4) g_sqp[z][gi0] = (&v.x)[dq];
        }
        if (gi0 + 1 < n) {
            float4 v; v.x = a1x; v.y = a1y; v.z = a1z; v.w = a1w;
            *(float4*)&gp[(size_t)(gi0 + 1) * n + gj0] = v;
            const int dq = gi0 + 1 - gj0;
            if (dq >= 0 && dq < 4) g_sqp[z][gi0 + 1] = (&v.x)[dq];
        }
    }
}

// ---------------------------------------------------------------------------
// Triplet: one block (128 thr) per j. Fused partial-sum + pd reconstruct,
// ballot compaction + warp-scan offsets, branch-free fp32 hot loop.
// ---------------------------------------------------------------------------
__global__ void triplet_kernel(const int* __restrict__ ind, int n) {
    __shared__ float    pdrow[MAX_N];
    __shared__ int      labs[MAX_N];
    __shared__ float    avals[POSCAP];
    __shared__ unsigned chunkMask[MAXW];
    __shared__ int      chunkOff[MAXW];
    __shared__ int      nSame;
    __shared__ float    red_s[4];
    __shared__ int      red_c[4];

    const int j    = blockIdx.x;
    const int tid  = threadIdx.x;
    const int lane = tid & 31;
    const int wid  = tid >> 5;

    // sqj read directly by every thread (broadcast LDG of partials)
    float sqj = g_sqp[0][j];
    #pragma unroll
    for (int z = 1; z < KSPLIT; z++) sqj += g_sqp[z][j];

    // fused: sum gram/sq partials and reconstruct pd row in one pass
    const size_t roff = (size_t)j * n;
    const int n4 = n >> 2;
    for (int v = tid; v < n4; v += 128) {
        float4 g = ((const float4*)(g_part[0] + roff))[v];
        float4 q = ((const float4*)g_sqp[0])[v];
        #pragma unroll
        for (int z = 1; z < KSPLIT; z++) {
            const float4 gz = ((const float4*)(g_part[z] + roff))[v];
            const float4 qz = ((const float4*)g_sqp[z])[v];
            g.x += gz.x; g.y += gz.y; g.z += gz.z; g.w += gz.w;
            q.x += qz.x; q.y += qz.y; q.z += qz.z; q.w += qz.w;
        }
        float4 pd;
        pd.x = fmaxf(fmaf(-2.f, g.x, sqj + q.x), 0.f);
        pd.y = fmaxf(fmaf(-2.f, g.y, sqj + q.y), 0.f);
        pd.z = fmaxf(fmaf(-2.f, g.z, sqj + q.z), 0.f);
        pd.w = fmaxf(fmaf(-2.f, g.w, sqj + q.w), 0.f);
        ((float4*)pdrow)[v] = pd;
    }
    for (int v = (n4 << 2) + tid; v < n; v += 128) {
        float g = 0.f, q = 0.f;
        #pragma unroll
        for (int z = 0; z < KSPLIT; z++) { g += g_part[z][roff + v]; q += g_sqp[z][v]; }
        pdrow[v] = fmaxf(fmaf(-2.f, g, sqj + q), 0.f);
    }
    for (int t = tid; t < n; t += 128)
        labs[t] = ind[t];
    __syncthreads();

    const int labj = labs[j];

    // ballot compaction of same-label i's (i != 0)
    const int nChunks = (n + 31) >> 5;
    for (int c = wid; c < nChunks; c += 4) {
        const int t = (c << 5) + lane;
        const bool pred = (t < n) && (t != 0) && (labs[t] == labj);
        const unsigned m = __ballot_sync(0xffffffffu, pred);
        if (lane == 0) chunkMask[c] = m;
    }
    __syncthreads();
    if (wid == 0) {                       // warp scan (nChunks <= 32)
        const unsigned m = (lane < nChunks) ? chunkMask[lane] : 0u;
        int p = __popc(m);
        #pragma unroll
        for (int o = 1; o < 32; o <<= 1) {
            const int t = __shfl_up_sync(0xffffffffu, p, o);
            if (lane >= o) p += t;
        }
        if (lane < nChunks) chunkOff[lane] = p - __popc(m);
        if (lane == 31) nSame = p;
    }
    __syncthreads();
    for (int c = wid; c < nChunks; c += 4) {
        const unsigned m = chunkMask[c];
        const int t = (c << 5) + lane;
        if ((m >> lane) & 1u) {
            const int off = chunkOff[c] + __popc(m & ((1u << lane) - 1u));
            if (off < POSCAP) avals[off] = pdrow[t] + MARGIN_A;
        }
    }
    __syncthreads();

    // this thread's diff-label pd values in 4 register slots
    float pdk[4];
    #pragma unroll
    for (int m = 0; m < 4; m++) pdk[m] = 3.4e38f;   // sentinel: never counted
    {
        int m = 0;
        for (int k = tid; k < n; k += 128, m++)
            if (labs[k] != labj) pdk[m] = pdrow[k];
    }

    const int ns = (nSame < POSCAP) ? nSame : POSCAP;
    float s = 0.f;
    int   c = 0;
    for (int q = 0; q < ns; q++) {
        const float aq = avals[q];
        #pragma unroll
        for (int m = 0; m < 4; m++) {
            const float v = aq - pdk[m];
            if (v > 0.f) { s += v; c++; }
        }
    }

    #pragma unroll
    for (int o = 16; o > 0; o >>= 1) {
        s += __shfl_down_sync(0xffffffffu, s, o);
        c += __shfl_down_sync(0xffffffffu, c, o);
    }
    if (lane == 0) { red_s[wid] = s; red_c[wid] = c; }
    __syncthreads();
    if (tid == 0) {
        float st = 0.f; int ct = 0;
        #pragma unroll
        for (int w = 0; w < 4; w++) { st += red_s[w]; ct += red_c[w]; }
        g_ps[j] = st;
        g_pc[j] = ct;
    }
}

// ---------------------------------------------------------------------------
// Final: single block, fp64 reduce of n partials.
// ---------------------------------------------------------------------------
__global__ void final_kernel(float* __restrict__ out, int n) {
    __shared__ double red_s[4];
    __shared__ double red_c[4];
    const int tid  = threadIdx.x;
    const int lane = tid & 31;
    const int wid  = tid >> 5;

    double s = 0.0, c = 0.0;
    for (int t = tid; t < n; t += 128) { s += (double)g_ps[t]; c += (double)g_pc[t]; }
    #pragma unroll
    for (int o = 16; o > 0; o >>= 1) {
        s += __shfl_down_sync(0xffffffffu, s, o);
        c += __shfl_down_sync(0xffffffffu, c, o);
    }
    if (lane == 0) { red_s[wid] = s; red_c[wid] = c; }
    __syncthreads();
    if (tid == 0) {
        double st = 0.0, ct = 0.0;
        #pragma unroll
        for (int w = 0; w < 4; w++) { st += red_s[w]; ct += red_c[w]; }
        out[0] = (ct > 0.0) ? (float)(st / (ct < 1.0 ? 1.0 : ct)) : 0.0f;
    }
}

extern "C" void kernel_launch(void* const* d_in, const int* in_sizes, int n_in,
                              void* d_out, int out_size) {
    const float* anchor   = (const float*)d_in[0];
    const float* positive = (const float*)d_in[1];
    const float* negative = (const float*)d_in[2];
    const int*   ind      = (const int*)d_in[3];

    const int n = in_sizes[3];          // 3B
    const int B = n / 3;
    const int D = in_sizes[0] / B;      // 128

    dim3 grid((n + TCN - 1) / TCN, (n + TR - 1) / TR, KSPLIT);  // 8x15x8 = 960
    gram_kernel<<<grid, 256>>>(anchor, positive, negative, n, B, D);
    triplet_kernel<<<n, 128>>>(ind, n);
    final_kernel<<<1, 128>>>((float*)d_out, n);
}

// round 12
// speedup vs baseline: 1.2429x; 1.1214x over previous
#include <cuda_runtime.h>
#include <cuda_bf16.h>

// ---------------------------------------------------------------------------
// HardTripletMiningLoss  (n=3B=480, D=128)
//   gram = E E^T ;  pd[i,j] = max(sq_i + sq_j - 2 gram_ij, 0)
//   loss = mean over {i!=0, lab[i]==lab[j], lab[k]!=lab[j], td>0} of
//          td = pd[i,j] - pd[j,k] + A
// R12: PDL (programmatic dependent launch) chains gram -> triplet -> final.
//      Triplet does ALL label work (ballot/scan/slist) BEFORE
//      griddepcontrol.wait so it overlaps gram execution; launch gaps of the
//      two dependent kernels are hidden. Kernels themselves = R11 (proven).
// ---------------------------------------------------------------------------

#define MAX_N    768
#define MAXW     ((MAX_N + 31) / 32)
#define POSCAP   128
#define MARGIN_A 0.2f
#define TR       32      // gram tile rows
#define TCN      64      // gram tile cols
#define KSPLIT   8
#define KC       16      // D / KSPLIT for D=128
#define ASTR     20      // As row stride (mult of 4 -> aligned float4 stores)

static __device__ float g_part[KSPLIT][MAX_N * MAX_N];
static __device__ float g_sqp [KSPLIT][MAX_N];
static __device__ float g_ps[MAX_N];
static __device__ int   g_pc[MAX_N];

__device__ __forceinline__ void pdl_wait() {
    asm volatile("griddepcontrol.wait;" ::: "memory");
}
__device__ __forceinline__ void pdl_launch_dependents() {
    asm volatile("griddepcontrol.launch_dependents;" ::: "memory");
}

__device__ __forceinline__ const float* row_ptr(const float* a, const float* p,
                                                const float* ng, int r, int B, int D) {
    if (r < B)      return a  + (size_t)r * D;
    if (r < 2 * B)  return p  + (size_t)(r - B) * D;
    return ng + (size_t)(r - 2 * B) * D;
}

// ---------------------------------------------------------------------------
// gram: grid (ceil(n/64), ceil(n/32), KSPLIT), 256 thr, 2 rows x 4 cols each.
// Inner loop per k: 2 broadcast LDS + 1 LDS.128 + 8 FMA.
// ---------------------------------------------------------------------------
__global__ void gram_kernel(const float* __restrict__ anchor,
                            const float* __restrict__ positive,
                            const float* __restrict__ negative,
                            int n, int B, int D) {
    __shared__ float As[TR][ASTR];      // row-major over k
    __shared__ float BsT[KC][TCN];      // k-major transposed

    const int bi  = blockIdx.y * TR;
    const int bj  = blockIdx.x * TCN;
    const int z   = blockIdx.z;
    const int Kc  = D / KSPLIT;          // 16
    const int k0  = z * Kc;
    const int tid = threadIdx.x;

    // load As: 32 rows x 4 float4
    if (tid < TR * 4) {
        const int r  = tid >> 2;
        const int c4 = tid & 3;
        const int gr = (bi + r < n) ? bi + r : n - 1;
        const float4 v = *(const float4*)(row_ptr(anchor, positive, negative, gr, B, D) + k0 + c4 * 4);
        *(float4*)&As[r][c4 * 4] = v;
    }
    // load BsT transposed: 64 cols x 4 float4 (one per thread)
    {
        const int col = tid & (TCN - 1);
        const int c4  = tid >> 6;        // 0..3
        const int gc  = (bj + col < n) ? bj + col : n - 1;
        const float4 v = *(const float4*)(row_ptr(anchor, positive, negative, gc, B, D) + k0 + c4 * 4);
        const int k = c4 * 4;
        BsT[k + 0][col] = v.x;
        BsT[k + 1][col] = v.y;
        BsT[k + 2][col] = v.z;
        BsT[k + 3][col] = v.w;
    }
    __syncthreads();

    const int tx = tid & 15;
    const int ty = tid >> 4;
    const int r0 = ty * 2;
    const int c0 = tx * 4;

    float a0x = 0.f, a0y = 0.f, a0z = 0.f, a0w = 0.f;
    float a1x = 0.f, a1y = 0.f, a1z = 0.f, a1w = 0.f;

    #pragma unroll
    for (int k = 0; k < KC; k++) {
        const float x0 = As[r0][k];                      // broadcast LDS
        const float x1 = As[r0 + 1][k];                  // broadcast LDS
        const float4 b = *(const float4*)&BsT[k][c0];    // conflict-free LDS.128
        a0x = fmaf(x0, b.x, a0x);
        a0y = fmaf(x0, b.y, a0y);
        a0z = fmaf(x0, b.z, a0z);
        a0w = fmaf(x0, b.w, a0w);
        a1x = fmaf(x1, b.x, a1x);
        a1y = fmaf(x1, b.y, a1y);
        a1z = fmaf(x1, b.z, a1z);
        a1w = fmaf(x1, b.w, a1w);
    }

    float* gp = g_part[z];
    const int gi0 = bi + r0;
    const int gj0 = bj + c0;
    if (gj0 < n) {                        // n%4==0 -> float4 in-bounds
        if (gi0 < n) {
            float4 v; v.x = a0x; v.y = a0y; v.z = a0z; v.w = a0w;
            *(float4*)&gp[(size_t)gi0 * n + gj0] = v;
            const int dq = gi0 - gj0;
            if (dq >= 0 && dq < 4) g_sqp[z][gi0] = (&v.x)[dq];
        }
        if (gi0 + 1 < n) {
            float4 v; v.x = a1x; v.y = a1y; v.z = a1z; v.w = a1w;
            *(float4*)&gp[(size_t)(gi0 + 1) * n + gj0] = v;
            const int dq = gi0 + 1 - gj0;
            if (dq >= 0 && dq < 4) g_sqp[z][gi0 + 1] = (&v.x)[dq];
        }
    }
    pdl_launch_dependents();              // writes above are visible to waiter
}

// ---------------------------------------------------------------------------
// Triplet: one block (128 thr) per j. Label work BEFORE pdl_wait (overlaps
// gram); gram-dependent work after. Branch-free fp32 hot loop.
// ---------------------------------------------------------------------------
__global__ void triplet_kernel(const int* __restrict__ ind, int n) {
    __shared__ float    pdrow[MAX_N];
    __shared__ int      labs[MAX_N];
    __shared__ short    slist[POSCAP];
    __shared__ float    avals[POSCAP];
    __shared__ unsigned chunkMask[MAXW];
    __shared__ int      chunkOff[MAXW];
    __shared__ int      nSame;
    __shared__ float    red_s[4];
    __shared__ int      red_c[4];

    const int j    = blockIdx.x;
    const int tid  = threadIdx.x;
    const int lane = tid & 31;
    const int wid  = tid >> 5;

    // ---------------- pre-wait: everything independent of gram --------------
    for (int t = tid; t < n; t += 128)
        labs[t] = ind[t];
    __syncthreads();

    const int labj = labs[j];

    const int nChunks = (n + 31) >> 5;
    for (int c = wid; c < nChunks; c += 4) {
        const int t = (c << 5) + lane;
        const bool pred = (t < n) && (t != 0) && (labs[t] == labj);
        const unsigned m = __ballot_sync(0xffffffffu, pred);
        if (lane == 0) chunkMask[c] = m;
    }
    __syncthreads();
    if (wid == 0) {                       // warp scan (nChunks <= 32)
        const unsigned m = (lane < nChunks) ? chunkMask[lane] : 0u;
        int p = __popc(m);
        #pragma unroll
        for (int o = 1; o < 32; o <<= 1) {
            const int t = __shfl_up_sync(0xffffffffu, p, o);
            if (lane >= o) p += t;
        }
        if (lane < nChunks) chunkOff[lane] = p - __popc(m);
        if (lane == 31) nSame = p;
    }
    __syncthreads();
    for (int c = wid; c < nChunks; c += 4) {
        const unsigned m = chunkMask[c];
        const int t = (c << 5) + lane;
        if ((m >> lane) & 1u) {
            const int off = chunkOff[c] + __popc(m & ((1u << lane) - 1u));
            if (off < POSCAP) slist[off] = (short)t;
        }
    }
    __syncthreads();

    // ---------------- wait for gram, then consume its output ----------------
    pdl_wait();

    float sqj = g_sqp[0][j];
    #pragma unroll
    for (int z = 1; z < KSPLIT; z++) sqj += g_sqp[z][j];

    const size_t roff = (size_t)j * n;
    const int n4 = n >> 2;
    for (int v = tid; v < n4; v += 128) {
        float4 g = ((const float4*)(g_part[0] + roff))[v];
        float4 q = ((const float4*)g_sqp[0])[v];
        #pragma unroll
        for (int z = 1; z < KSPLIT; z++) {
            const float4 gz = ((const float4*)(g_part[z] + roff))[v];
            const float4 qz = ((const float4*)g_sqp[z])[v];
            g.x += gz.x; g.y += gz.y; g.z += gz.z; g.w += gz.w;
            q.x += qz.x; q.y += qz.y; q.z += qz.z; q.w += qz.w;
        }
        float4 pd;
        pd.x = fmaxf(fmaf(-2.f, g.x, sqj + q.x), 0.f);
        pd.y = fmaxf(fmaf(-2.f, g.y, sqj + q.y), 0.f);
        pd.z = fmaxf(fmaf(-2.f, g.z, sqj + q.z), 0.f);
        pd.w = fmaxf(fmaf(-2.f, g.w, sqj + q.w), 0.f);
        ((float4*)pdrow)[v] = pd;
    }
    for (int v = (n4 << 2) + tid; v < n; v += 128) {
        float g = 0.f, q = 0.f;
        #pragma unroll
        for (int z = 0; z < KSPLIT; z++) { g += g_part[z][roff + v]; q += g_sqp[z][v]; }
        pdrow[v] = fmaxf(fmaf(-2.f, g, sqj + q), 0.f);
    }
    __syncthreads();

    const int ns = (nSame < POSCAP) ? nSame : POSCAP;
    if (tid < ns)
        avals[tid] = pdrow[(int)slist[tid]] + MARGIN_A;

    float pdk[4];
    #pragma unroll
    for (int m = 0; m < 4; m++) pdk[m] = 3.4e38f;   // sentinel: never counted
    {
        int m = 0;
        for (int k = tid; k < n; k += 128, m++)
            if (labs[k] != labj) pdk[m] = pdrow[k];
    }
    __syncthreads();

    float s = 0.f;
    int   c = 0;
    for (int q = 0; q < ns; q++) {
        const float aq = avals[q];
        #pragma unroll
        for (int m = 0; m < 4; m++) {
            const float v = aq - pdk[m];
            if (v > 0.f) { s += v; c++; }
        }
    }

    #pragma unroll
    for (int o = 16; o > 0; o >>= 1) {
        s += __shfl_down_sync(0xffffffffu, s, o);
        c += __shfl_down_sync(0xffffffffu, c, o);
    }
    if (lane == 0) { red_s[wid] = s; red_c[wid] = c; }
    __syncthreads();
    if (tid == 0) {
        float st = 0.f; int ct = 0;
        #pragma unroll
        for (int w = 0; w < 4; w++) { st += red_s[w]; ct += red_c[w]; }
        g_ps[j] = st;
        g_pc[j] = ct;
    }
    pdl_launch_dependents();
}

// ---------------------------------------------------------------------------
// Final: single block, fp64 reduce of n partials (waits on triplet via PDL).
// ---------------------------------------------------------------------------
__global__ void final_kernel(float* __restrict__ out, int n) {
    __shared__ double red_s[4];
    __shared__ double red_c[4];
    const int tid  = threadIdx.x;
    const int lane = tid & 31;
    const int wid  = tid >> 5;

    pdl_wait();

    double s = 0.0, c = 0.0;
    for (int t = tid; t < n; t += 128) { s += (double)g_ps[t]; c += (double)g_pc[t]; }
    #pragma unroll
    for (int o = 16; o > 0; o >>= 1) {
        s += __shfl_down_sync(0xffffffffu, s, o);
        c += __shfl_down_sync(0xffffffffu, c, o);
    }
    if (lane == 0) { red_s[wid] = s; red_c[wid] = c; }
    __syncthreads();
    if (tid == 0) {
        double st = 0.0, ct = 0.0;
        #pragma unroll
        for (int w = 0; w < 4; w++) { st += red_s[w]; ct += red_c[w]; }
        out[0] = (ct > 0.0) ? (float)(st / (ct < 1.0 ? 1.0 : ct)) : 0.0f;
    }
}

extern "C" void kernel_launch(void* const* d_in, const int* in_sizes, int n_in,
                              void* d_out, int out_size) {
    const float* anchor   = (const float*)d_in[0];
    const float* positive = (const float*)d_in[1];
    const float* negative = (const float*)d_in[2];
    const int*   ind      = (const int*)d_in[3];

    const int n = in_sizes[3];          // 3B
    const int B = n / 3;
    const int D = in_sizes[0] / B;      // 128

    dim3 ggrid((n + TCN - 1) / TCN, (n + TR - 1) / TR, KSPLIT);  // 8x15x8
    gram_kernel<<<ggrid, 256>>>(anchor, positive, negative, n, B, D);

    cudaLaunchAttribute attr[1];
    attr[0].id = cudaLaunchAttributeProgrammaticStreamSerialization;
    attr[0].val.programmaticStreamSerializationAllowed = 1;

    cudaLaunchConfig_t cfg = {};
    cfg.attrs = attr;
    cfg.numAttrs = 1;
    cfg.stream = 0;

    cfg.gridDim  = dim3((unsigned)n, 1, 1);
    cfg.blockDim = dim3(128, 1, 1);
    cudaLaunchKernelEx(&cfg, triplet_kernel, ind, n);

    cfg.gridDim  = dim3(1, 1, 1);
    cfg.blockDim = dim3(128, 1, 1);
    cudaLaunchKernelEx(&cfg, final_kernel, (float*)d_out, n);
}